// round 11
// baseline (speedup 1.0000x reference)
#include <cuda_runtime.h>
#include <cuda_fp16.h>
#include <cstdint>

#define Nn 100000
#define Mm 800000
#define CAP 48

// ---------------- device scratch (no allocations allowed) ----------------
__device__ __half    g_h2h[(size_t)Nn * 64];     // h2 rows fp16 (identity col order)
__device__ __half    g_xh[(size_t)Nn * 64];      // x rows fp16 (identity col order)
__device__ uint32_t  g_aggEh[(size_t)Nn * 32];   // aggE fp16 rows + counts (words 24,25), pad 0
__device__ int       g_cur[Nn];                  // degree cursor
__device__ int       g_slots[(size_t)Nn * CAP];  // edge id per bucket slot
__device__ int       g_slots2[(size_t)Nn * CAP]; // src node per bucket slot
__device__ int       g_ovf_cnt;
__device__ int2      g_ovf[8192];                // overflow: (edge id, dst)

__device__ __forceinline__ void mma_f16(float c[4], uint32_t a0, uint32_t a1,
                                        uint32_t a2, uint32_t a3,
                                        uint32_t b0, uint32_t b1) {
    asm volatile(
        "mma.sync.aligned.m16n8k16.row.col.f32.f16.f16.f32 "
        "{%0,%1,%2,%3},{%4,%5,%6,%7},{%8,%9},{%0,%1,%2,%3};"
        : "+f"(c[0]), "+f"(c[1]), "+f"(c[2]), "+f"(c[3])
        : "r"(a0), "r"(a1), "r"(a2), "r"(a3), "r"(b0), "r"(b1));
}

__device__ __forceinline__ uint32_t pack_h2(float a, float b) {
    __half2 h = __floats2half2_rn(a, b);
    return *(uint32_t*)&h;
}

// ---------------- kernels ----------------

__global__ void zero_kernel() {
    int gid = blockIdx.x * blockDim.x + threadIdx.x;
    int stride = gridDim.x * blockDim.x;
    for (int i = gid; i < Nn; i += stride) g_cur[i] = 0;
    if (gid == 0) g_ovf_cnt = 0;
}

// 1 thread/edge: cursor bump + store edge id and src into buckets.
__global__ void edge_fill_kernel(const int* __restrict__ esrc,
                                 const int* __restrict__ edst) {
    int e = blockIdx.x * blockDim.x + threadIdx.x;
    if (e >= Mm) return;
    int dst = edst[e];
    int p = atomicAdd(&g_cur[dst], 1);
    if (p < CAP) {
        g_slots[(size_t)dst * CAP + p]  = e;
        g_slots2[(size_t)dst * CAP + p] = esrc[e];
    } else {
        int o = atomicAdd(&g_ovf_cnt, 1);
        if (o < 8192) g_ovf[o] = make_int2(e, dst);
    }
}

// Per-node reduction of edge features by etype. 8 lanes/node.
// Output row (32 words): word t*8+q = half2(ef_sum[t][2q], ef_sum[t][2q+1]),
// word 24 = half2(c0,c1), word 25 = half2(c2,0), words 26..31 = 0.
__global__ __launch_bounds__(256)
void gatherE_kernel(const float* __restrict__ ef,
                    const int* __restrict__ etype) {
    int tid = threadIdx.x;
    int node = blockIdx.x * 32 + (tid >> 3);
    int q = tid & 7;
    if (node >= Nn) return;
    int deg = g_cur[node];
    if (deg > CAP) deg = CAP;

    const int* sl = &g_slots[(size_t)node * CAP];
    const float2* ef2 = (const float2*)ef;
    float aE[6] = {0.f, 0.f, 0.f, 0.f, 0.f, 0.f};
    int c1 = 0, c2 = 0;

    int i = 0;
    for (; i + 4 <= deg; i += 4) {
        int e[4], t[4];
        float2 v[4];
        #pragma unroll
        for (int u = 0; u < 4; u++) e[u] = __ldg(&sl[i + u]);
        #pragma unroll
        for (int u = 0; u < 4; u++) { t[u] = __ldg(&etype[e[u]]); v[u] = __ldg(&ef2[(size_t)e[u] * 8 + q]); }
        #pragma unroll
        for (int u = 0; u < 4; u++) {
            aE[2 * t[u]]     += v[u].x;
            aE[2 * t[u] + 1] += v[u].y;
            c1 += (t[u] == 1); c2 += (t[u] == 2);
        }
    }
    for (; i < deg; i++) {
        int e = __ldg(&sl[i]);
        int t = __ldg(&etype[e]);
        float2 v = __ldg(&ef2[(size_t)e * 8 + q]);
        aE[2 * t] += v.x; aE[2 * t + 1] += v.y;
        c1 += (t == 1); c2 += (t == 2);
    }

    uint32_t* row = g_aggEh + (size_t)node * 32;
    #pragma unroll
    for (int t = 0; t < 3; t++)
        row[t * 8 + q] = pack_h2(aE[2 * t], aE[2 * t + 1]);
    if (q == 0) {
        row[24] = pack_h2((float)(deg - c1 - c2), (float)c1);
        row[25] = pack_h2((float)c2, 0.f);
    } else if (q >= 2) {
        row[24 + q] = 0u;    // words 26..31
    }
}

// h2 GEMM: out-of-edge-path. A = [x*(t==0) | x*(t==1)] k=128 (fp32 x, float4
// loads, own fragment permutation). Writes h2h (fp16) AND x in fp16 (g_xh,
// identity word order) for h1's cheap loads.
__global__ __launch_bounds__(256, 2)
void h2_gemm_kernel(const float* __restrict__ x,
                    const int* __restrict__ ntype,
                    const float* __restrict__ W2, const float* __restrict__ b2) {
    extern __shared__ uint32_t smu[];
    uint4* Wf = (uint4*)smu;                 // [8][4][32] uint4 = 16 KB
    float* bc = (float*)(smu + 4096);        // [128]

    const int tid = threadIdx.x;
    const int w = tid >> 5, lane = tid & 31;
    const int g = lane >> 2, tq = lane & 3;

    // B fill, permuted to match float4 A loads:
    // fragment (kb, tqf, h, elem) <-> x col 16*(kb&3) + 4*tqf + 2*h + elem.
    for (int idx = tid; idx < 1024; idx += 256) {
        int ln = idx & 31;
        int ntp = (idx >> 5) & 3;
        int kb = idx >> 7;                    // 0..7
        int tqf = ln & 3, gf = ln >> 2;
        int ty = kb >> 2, p = kb & 3;
        int col0 = (2 * ntp) * 8 + gf;
        int col1 = col0 + 8;
        auto wv2 = [&](int h, int outc) -> uint32_t {
            int ca = 16 * p + 4 * tqf + 2 * h;
            return pack_h2(W2[(size_t)ty * 4096 + ca * 64 + outc],
                           W2[(size_t)ty * 4096 + (ca + 1) * 64 + outc]);
        };
        uint4 wv;
        wv.x = wv2(0, col0); wv.y = wv2(1, col0);
        wv.z = wv2(0, col1); wv.w = wv2(1, col1);
        Wf[idx] = wv;
    }
    if (tid < 128) bc[tid] = b2[tid];
    __syncthreads();

    const int G = Nn >> 4;
    const int nwarps = gridDim.x << 3;
    __half2* h2p = (__half2*)g_h2h;
    uint32_t* xh32 = (uint32_t*)g_xh;
    const float4* xp4 = (const float4*)x;

    for (int grp = blockIdx.x * 8 + w; grp < G; grp += nwarps) {
        int base = grp << 4;
        uint32_t xw[2][8], msk[2];
        int tt[2];
        #pragma unroll
        for (int j = 0; j < 2; j++) {
            int node = base + g + 8 * j;
            tt[j] = __ldg(&ntype[node]);
            msk[j] = (tt[j] == 0) ? 0xFFFFFFFFu : 0u;
            #pragma unroll
            for (int m = 0; m < 4; m++) {
                float4 f = xp4[(size_t)node * 16 + 4 * m + tq];
                xw[j][2 * m]     = pack_h2(f.x, f.y);   // word 8m+2tq
                xw[j][2 * m + 1] = pack_h2(f.z, f.w);   // word 8m+2tq+1
            }
        }

        float acc[8][4];
        #pragma unroll
        for (int nt = 0; nt < 8; nt++)
            #pragma unroll
            for (int jj = 0; jj < 4; jj++) acc[nt][jj] = 0.f;

        #pragma unroll
        for (int kb = 0; kb < 8; kb++) {
            int p = kb & 3;
            uint32_t s0 = (kb < 4) ? msk[0] : ~msk[0];
            uint32_t s1 = (kb < 4) ? msk[1] : ~msk[1];
            uint32_t a0 = xw[0][2 * p] & s0;
            uint32_t a2 = xw[0][2 * p + 1] & s0;
            uint32_t a1 = xw[1][2 * p] & s1;
            uint32_t a3 = xw[1][2 * p + 1] & s1;
            #pragma unroll
            for (int ntp = 0; ntp < 4; ntp++) {
                uint4 bw = Wf[(kb * 4 + ntp) * 32 + lane];
                mma_f16(acc[2 * ntp], a0, a1, a2, a3, bw.x, bw.y);
                mma_f16(acc[2 * ntp + 1], a0, a1, a2, a3, bw.z, bw.w);
            }
        }

        #pragma unroll
        for (int j = 0; j < 2; j++) {
            int node = base + g + 8 * j;
            int t = tt[j];
            // store fp16 x copy (identity word order: word w = cols 2w,2w+1)
            uint2* xdst = (uint2*)(xh32 + (size_t)node * 32);
            #pragma unroll
            for (int m = 0; m < 4; m++)
                xdst[(8 * m + 2 * tq) >> 1] = make_uint2(xw[j][2 * m], xw[j][2 * m + 1]);
            #pragma unroll
            for (int nt = 0; nt < 8; nt++) {
                int col0 = nt * 8 + 2 * tq;
                float v0 = acc[nt][2 * j + 0] + bc[t * 64 + col0];
                float v1 = acc[nt][2 * j + 1] + bc[t * 64 + col0 + 1];
                h2p[(size_t)node * 32 + nt * 4 + tq] = __floats2half2_rn(v0, v1);
            }
        }
    }
}

// Per-node h2 gather: out[node] = sum over bucket of h2h[src]. FULL write.
__global__ __launch_bounds__(256)
void gatherH_kernel(float* __restrict__ out) {
    int tid = threadIdx.x;
    int node = blockIdx.x * 32 + (tid >> 3);
    int q = tid & 7;
    if (node >= Nn) return;
    int deg = g_cur[node];
    if (deg > CAP) deg = CAP;

    const uint4* H = (const uint4*)g_h2h;
    const int* sl = &g_slots2[(size_t)node * CAP];
    float acc[8];
    #pragma unroll
    for (int u = 0; u < 8; u++) acc[u] = 0.f;

    auto add8 = [&](uint4 hv) {
        float2 f0 = __half22float2(*(__half2*)&hv.x);
        float2 f1 = __half22float2(*(__half2*)&hv.y);
        float2 f2 = __half22float2(*(__half2*)&hv.z);
        float2 f3 = __half22float2(*(__half2*)&hv.w);
        acc[0] += f0.x; acc[1] += f0.y; acc[2] += f1.x; acc[3] += f1.y;
        acc[4] += f2.x; acc[5] += f2.y; acc[6] += f3.x; acc[7] += f3.y;
    };

    int i = 0;
    for (; i + 8 <= deg; i += 8) {
        int s[8];
        #pragma unroll
        for (int u = 0; u < 8; u++) s[u] = __ldg(&sl[i + u]);
        uint4 v[8];
        #pragma unroll
        for (int u = 0; u < 8; u++) v[u] = __ldg(&H[(size_t)s[u] * 8 + q]);
        #pragma unroll
        for (int u = 0; u < 8; u++) add8(v[u]);
    }
    for (; i + 4 <= deg; i += 4) {
        int s[4];
        #pragma unroll
        for (int u = 0; u < 4; u++) s[u] = __ldg(&sl[i + u]);
        uint4 v[4];
        #pragma unroll
        for (int u = 0; u < 4; u++) v[u] = __ldg(&H[(size_t)s[u] * 8 + q]);
        #pragma unroll
        for (int u = 0; u < 4; u++) add8(v[u]);
    }
    for (; i < deg; i++) add8(__ldg(&H[(size_t)__ldg(&sl[i]) * 8 + q]));

    float4* o4 = (float4*)out;
    o4[(size_t)node * 16 + 2 * q]     = make_float4(acc[0], acc[1], acc[2], acc[3]);
    o4[(size_t)node * 16 + 2 * q + 1] = make_float4(acc[4], acc[5], acc[6], acc[7]);
}

// h1 GEMM: A = [x*(t==0)(64) | x*(t==1)(64) | tail(64)], k=192, fp16 inputs
// via uint4 loads (words 4u..4u+3, u = tq and tq+4), fragment mapping:
//   slot p in {0..3}: word(p, h) = 16*(p>>1) + 4*tq + 2*(p&1) + h.
// B built with matching permutation. Epilogue: out[node] += acc + b1[t].
__global__ __launch_bounds__(256, 2)
void h1_gemm_kernel(const int* __restrict__ ntype,
                    const float* __restrict__ W1, const float* __restrict__ b1,
                    const float* __restrict__ W5, const float* __restrict__ b5,
                    float* __restrict__ out) {
    extern __shared__ uint32_t smu[];
    uint4* Wf = (uint4*)smu;                 // [12][4][32] uint4 = 24 KB
    float* bc = (float*)(smu + 6144);        // [128]

    const int tid = threadIdx.x;
    const int w = tid >> 5, lane = tid & 31;
    const int g = lane >> 2, tq = lane & 3;

    for (int idx = tid; idx < 1536; idx += 256) {
        int ln = idx & 31;
        int ntp = (idx >> 5) & 3;
        int kb = idx >> 7;                    // 0..11
        int tqf = ln & 3, gf = ln >> 2;
        int col0 = (2 * ntp) * 8 + gf;
        int col1 = col0 + 8;
        auto val = [&](int h, int elem, int outc) -> float {
            if (kb < 8) {
                int ty = kb >> 2, p = kb & 3;
                int wd = 16 * (p >> 1) + 4 * tqf + 2 * (p & 1) + h;
                int hh = 2 * wd + elem;                      // x column
                return W1[(size_t)ty * 4096 + hh * 64 + outc];
            } else {
                int p = kb - 8;
                int wd = 16 * (p >> 1) + 4 * tqf + 2 * (p & 1) + h;
                if (wd < 24) {
                    int t = wd >> 3, colf = 2 * (wd & 7) + elem;
                    return W5[(size_t)(t * 16 + colf) * 64 + outc];
                }
                if (wd == 24) return b5[elem * 64 + outc];           // c0->b5[0], c1->b5[1]
                if (wd == 25) return (elem == 0) ? b5[128 + outc] : 0.f;  // c2->b5[2]
                return 0.f;
            }
        };
        uint4 wv;
        wv.x = pack_h2(val(0, 0, col0), val(0, 1, col0));
        wv.y = pack_h2(val(1, 0, col0), val(1, 1, col0));
        wv.z = pack_h2(val(0, 0, col1), val(0, 1, col1));
        wv.w = pack_h2(val(1, 0, col1), val(1, 1, col1));
        Wf[idx] = wv;
    }
    if (tid < 128) bc[tid] = b1[tid];
    __syncthreads();

    const int G = Nn >> 4;
    const int nwarps = gridDim.x << 3;
    float2* outp = (float2*)out;
    const uint4* xh4 = (const uint4*)g_xh;
    const uint4* ag4 = (const uint4*)g_aggEh;

    for (int grp = blockIdx.x * 8 + w; grp < G; grp += nwarps) {
        int base = grp << 4;
        uint4 xu[2][2], tu[2][2];
        uint32_t msk[2];
        int tt[2];
        #pragma unroll
        for (int j = 0; j < 2; j++) {
            int node = base + g + 8 * j;
            tt[j] = __ldg(&ntype[node]);
            msk[j] = (tt[j] == 0) ? 0xFFFFFFFFu : 0u;
            xu[j][0] = __ldg(&xh4[(size_t)node * 8 + tq]);
            xu[j][1] = __ldg(&xh4[(size_t)node * 8 + tq + 4]);
            tu[j][0] = __ldg(&ag4[(size_t)node * 8 + tq]);
            tu[j][1] = __ldg(&ag4[(size_t)node * 8 + tq + 4]);
        }

        float acc[8][4];
        #pragma unroll
        for (int nt = 0; nt < 8; nt++)
            #pragma unroll
            for (int jj = 0; jj < 4; jj++) acc[nt][jj] = 0.f;

        // slot extraction: p=0 -> (u0.x,u0.y), p=1 -> (u0.z,u0.w),
        //                  p=2 -> (u1.x,u1.y), p=3 -> (u1.z,u1.w)
        auto slot = [&](uint4 uq[2], int p, int h) -> uint32_t {
            uint4 uu = uq[p >> 1];
            return (p & 1) ? (h ? uu.w : uu.z) : (h ? uu.y : uu.x);
        };

        #pragma unroll
        for (int kb = 0; kb < 12; kb++) {
            uint32_t a0, a1, a2, a3;
            if (kb < 8) {
                int p = kb & 3;
                uint32_t s0 = (kb < 4) ? msk[0] : ~msk[0];
                uint32_t s1 = (kb < 4) ? msk[1] : ~msk[1];
                a0 = slot(xu[0], p, 0) & s0;
                a2 = slot(xu[0], p, 1) & s0;
                a1 = slot(xu[1], p, 0) & s1;
                a3 = slot(xu[1], p, 1) & s1;
            } else {
                int p = kb - 8;
                a0 = slot(tu[0], p, 0); a2 = slot(tu[0], p, 1);
                a1 = slot(tu[1], p, 0); a3 = slot(tu[1], p, 1);
            }
            #pragma unroll
            for (int ntp = 0; ntp < 4; ntp++) {
                uint4 bw = Wf[(kb * 4 + ntp) * 32 + lane];
                mma_f16(acc[2 * ntp], a0, a1, a2, a3, bw.x, bw.y);
                mma_f16(acc[2 * ntp + 1], a0, a1, a2, a3, bw.z, bw.w);
            }
        }

        #pragma unroll
        for (int j = 0; j < 2; j++) {
            int node = base + g + 8 * j;
            int t = tt[j];
            #pragma unroll
            for (int nt = 0; nt < 8; nt++) {
                int col0 = nt * 8 + 2 * tq;
                size_t oidx = (size_t)node * 32 + nt * 4 + tq;
                float2 o = outp[oidx];
                o.x += acc[nt][2 * j + 0] + bc[t * 64 + col0];
                o.y += acc[nt][2 * j + 1] + bc[t * 64 + col0 + 1];
                outp[oidx] = o;
            }
        }
    }
}

// Overflow edges: add W2[t]*x[src] + b2[t] + W5[et]*ef[e] + b5[et] to out[dst].
__global__ void ovf_kernel(const float* __restrict__ x,
                           const int* __restrict__ ntype,
                           const int* __restrict__ esrc,
                           const int* __restrict__ etype,
                           const float* __restrict__ ef,
                           const float* __restrict__ W2, const float* __restrict__ b2,
                           const float* __restrict__ W5, const float* __restrict__ b5,
                           float* __restrict__ out) {
    int n = g_ovf_cnt;
    if (n > 8192) n = 8192;
    int wid = (blockIdx.x * blockDim.x + threadIdx.x) >> 5;
    int lane = threadIdx.x & 31;
    int nwarps = (gridDim.x * blockDim.x) >> 5;
    for (int ei = wid; ei < n; ei += nwarps) {
        int2 ed = g_ovf[ei];
        int e = ed.x, dst = ed.y;
        int src = esrc[e];
        int t = ntype[src];
        int et = etype[e];
        int c = lane * 2;
        float s0 = b2[t * 64 + c] + b5[et * 64 + c];
        float s1 = b2[t * 64 + c + 1] + b5[et * 64 + c + 1];
        for (int k = 0; k < 64; k++) {
            float xv = __ldg(&x[(size_t)src * 64 + k]);
            s0 += xv * __ldg(&W2[(size_t)t * 4096 + k * 64 + c]);
            s1 += xv * __ldg(&W2[(size_t)t * 4096 + k * 64 + c + 1]);
        }
        for (int f = 0; f < 16; f++) {
            float v = __ldg(&ef[(size_t)e * 16 + f]);
            s0 += v * __ldg(&W5[(size_t)(et * 16 + f) * 64 + c]);
            s1 += v * __ldg(&W5[(size_t)(et * 16 + f) * 64 + c + 1]);
        }
        atomicAdd(&out[(size_t)dst * 64 + c], s0);
        atomicAdd(&out[(size_t)dst * 64 + c + 1], s1);
    }
}

// ---------------- launch ----------------
extern "C" void kernel_launch(void* const* d_in, const int* in_sizes, int n_in,
                              void* d_out, int out_size) {
    const float *x = nullptr, *ef = nullptr;
    const float *W[4] = {nullptr, nullptr, nullptr, nullptr};
    const float *B[4] = {nullptr, nullptr, nullptr, nullptr};
    const float *W5 = nullptr, *b5 = nullptr;
    const int *ntype = nullptr, *esrc = nullptr, *edst = nullptr, *etype = nullptr;
    int wI = 0, bI = 0, mI = 0;
    for (int i = 0; i < n_in; i++) {
        long s = in_sizes[i];
        const void* p = d_in[i];
        if (s == (long)Nn * 64)       x = (const float*)p;
        else if (s == (long)Mm * 16)  ef = (const float*)p;
        else if (s == Nn)             ntype = (const int*)p;
        else if (s == Mm) {
            if (mI == 0) esrc = (const int*)p;
            else if (mI == 1) edst = (const int*)p;
            else etype = (const int*)p;
            mI++;
        }
        else if (s == 2 * 64 * 64) { if (wI < 4) W[wI++] = (const float*)p; }
        else if (s == 2 * 64)      { if (bI < 4) B[bI++] = (const float*)p; }
        else if (s == 3 * 16 * 64) W5 = (const float*)p;
        else if (s == 3 * 64)      b5 = (const float*)p;
    }
    float* out = (float*)d_out;

    cudaStream_t s2;
    cudaEvent_t evFork, evE;
    bool forked = (cudaStreamCreateWithFlags(&s2, cudaStreamNonBlocking) == cudaSuccess)
               && (cudaEventCreateWithFlags(&evFork, cudaEventDisableTiming) == cudaSuccess)
               && (cudaEventCreateWithFlags(&evE, cudaEventDisableTiming) == cudaSuccess);

    const int h2_smem = 4096 * 4 + 128 * 4;   // 16.5 KB
    const int h1_smem = 6144 * 4 + 128 * 4;   // 24.5 KB

    if (forked) {
        cudaEventRecord(evFork, 0);
        cudaStreamWaitEvent(s2, evFork, 0);
        // side: edge path (independent of h2 GEMM)
        zero_kernel<<<512, 256, 0, s2>>>();
        edge_fill_kernel<<<(Mm + 255) / 256, 256, 0, s2>>>(esrc, edst);
        gatherE_kernel<<<(Nn + 31) / 32, 256, 0, s2>>>(ef, etype);
        cudaEventRecord(evE, s2);
        // main: h2 GEMM (148 blocks: leaves SM space for the side stream)
        h2_gemm_kernel<<<148, 256, h2_smem>>>(x, ntype, W[1], B[1]);
        cudaStreamWaitEvent(0, evE, 0);
    } else {
        zero_kernel<<<512, 256>>>();
        edge_fill_kernel<<<(Mm + 255) / 256, 256>>>(esrc, edst);
        gatherE_kernel<<<(Nn + 31) / 32, 256>>>(ef, etype);
        h2_gemm_kernel<<<148, 256, h2_smem>>>(x, ntype, W[1], B[1]);
    }

    gatherH_kernel<<<(Nn + 31) / 32, 256>>>(out);
    h1_gemm_kernel<<<296, 256, h1_smem>>>(ntype, W[0], B[0], W5, b5, out);
    ovf_kernel<<<8, 256>>>(x, ntype, esrc, etype, ef, W[1], B[1], W5, b5, out);
}

// round 12
// speedup vs baseline: 1.3605x; 1.3605x over previous
#include <cuda_runtime.h>
#include <cuda_fp16.h>
#include <cstdint>

#define Nn 100000
#define Mm 800000
#define CAP 48

// ---------------- device scratch (no allocations allowed) ----------------
__device__ __half    g_h2h[(size_t)Nn * 64];    // h2 rows fp16 (identity col order)
__device__ __half    g_xh[(size_t)Nn * 64];     // x rows fp16 (identity col order)
__device__ uint32_t  g_aggEh[(size_t)Nn * 32];  // fp16 aggE rows [t*8+q]=pair(2q,2q+1); words 24..31 pad
__device__ int       g_cur[Nn];                 // packed: tot(10)|c1(10)|c2(10)
__device__ int       g_slots[(size_t)Nn * CAP]; // src node per bucket slot
__device__ int       g_ovf_cnt;
__device__ int2      g_ovf[8192];               // overflow: (src, dst)

__device__ __forceinline__ void red_add_h8(uint32_t* p, uint32_t a, uint32_t b,
                                           uint32_t c, uint32_t d) {
    asm volatile("red.global.add.noftz.v4.f16x2 [%0], {%1,%2,%3,%4};"
                 :: "l"(p), "r"(a), "r"(b), "r"(c), "r"(d) : "memory");
}

__device__ __forceinline__ void mma_f16(float c[4], uint32_t a0, uint32_t a1,
                                        uint32_t a2, uint32_t a3,
                                        uint32_t b0, uint32_t b1) {
    asm volatile(
        "mma.sync.aligned.m16n8k16.row.col.f32.f16.f16.f32 "
        "{%0,%1,%2,%3},{%4,%5,%6,%7},{%8,%9},{%0,%1,%2,%3};"
        : "+f"(c[0]), "+f"(c[1]), "+f"(c[2]), "+f"(c[3])
        : "r"(a0), "r"(a1), "r"(a2), "r"(a3), "r"(b0), "r"(b1));
}

__device__ __forceinline__ uint32_t pack_h2(float a, float b) {
    __half2 h = __floats2half2_rn(a, b);
    return *(uint32_t*)&h;
}

// ---------------- kernels ----------------

__global__ void zero_kernel() {
    int gid = blockIdx.x * blockDim.x + threadIdx.x;
    int stride = gridDim.x * blockDim.x;
    uint4 z = make_uint4(0u, 0u, 0u, 0u);
    uint4* a4 = (uint4*)g_aggEh;
    for (int i = gid; i < Nn * 8; i += stride) a4[i] = z;
    for (int i = gid; i < Nn; i += stride) g_cur[i] = 0;
    if (gid == 0) g_ovf_cnt = 0;
}

// 2 threads/edge: fp16x8 red into aggE row + packed cursor + bucket fill
__global__ void edge_scatter_kernel(const float* __restrict__ ef,
                                    const int* __restrict__ esrc,
                                    const int* __restrict__ edst,
                                    const int* __restrict__ etype) {
    int gid = blockIdx.x * blockDim.x + threadIdx.x;
    int e = gid >> 1, q = gid & 1;
    if (e >= Mm) return;
    int dst = edst[e];
    int t   = etype[e];
    const float4* ef4 = (const float4*)ef;
    float4 v0 = ef4[e * 4 + q * 2];
    float4 v1 = ef4[e * 4 + q * 2 + 1];
    uint32_t h0 = pack_h2(v0.x, v0.y), h1 = pack_h2(v0.z, v0.w);
    uint32_t h2 = pack_h2(v1.x, v1.y), h3 = pack_h2(v1.z, v1.w);
    red_add_h8(g_aggEh + (size_t)dst * 32 + t * 8 + q * 4, h0, h1, h2, h3);
    if (q == 0) {
        int inc = 1 + ((t == 1) ? (1 << 10) : 0) + ((t == 2) ? (1 << 20) : 0);
        int old = atomicAdd(&g_cur[dst], inc);
        int p = old & 1023;
        int src = esrc[e];
        if (p < CAP) {
            g_slots[(size_t)dst * CAP + p] = src;
        } else {
            int o = atomicAdd(&g_ovf_cnt, 1);
            if (o < 8192) g_ovf[o] = make_int2(src, dst);
        }
    }
}

// h2 GEMM (side stream): A = [x*(t==0) | x*(t==1)] k=128, fp32 x via float4,
// own fragment permutation. Writes h2h (fp16) AND x as fp16 (g_xh, identity
// word order) for h1's cheap loads.
__global__ __launch_bounds__(256, 2)
void h2_gemm_kernel(const float* __restrict__ x,
                    const int* __restrict__ ntype,
                    const float* __restrict__ W2, const float* __restrict__ b2) {
    extern __shared__ uint32_t smu[];
    uint4* Wf = (uint4*)smu;                 // [8][4][32] uint4 = 16 KB
    float* bc = (float*)(smu + 4096);        // [128]

    const int tid = threadIdx.x;
    const int w = tid >> 5, lane = tid & 31;
    const int g = lane >> 2, tq = lane & 3;

    // B fill, permuted to match float4 A loads:
    // fragment (kb, tqf, h, elem) <-> x col 16*(kb&3) + 4*tqf + 2*h + elem.
    for (int idx = tid; idx < 1024; idx += 256) {
        int ln = idx & 31;
        int ntp = (idx >> 5) & 3;
        int kb = idx >> 7;                    // 0..7
        int tqf = ln & 3, gf = ln >> 2;
        int ty = kb >> 2, p = kb & 3;
        int col0 = (2 * ntp) * 8 + gf;
        int col1 = col0 + 8;
        auto wv2 = [&](int h, int outc) -> uint32_t {
            int ca = 16 * p + 4 * tqf + 2 * h;
            return pack_h2(W2[(size_t)ty * 4096 + ca * 64 + outc],
                           W2[(size_t)ty * 4096 + (ca + 1) * 64 + outc]);
        };
        uint4 wv;
        wv.x = wv2(0, col0); wv.y = wv2(1, col0);
        wv.z = wv2(0, col1); wv.w = wv2(1, col1);
        Wf[idx] = wv;
    }
    if (tid < 128) bc[tid] = b2[tid];
    __syncthreads();

    const int G = Nn >> 4;
    const int nwarps = gridDim.x << 3;
    __half2* h2p = (__half2*)g_h2h;
    uint32_t* xh32 = (uint32_t*)g_xh;
    const float4* xp4 = (const float4*)x;

    for (int grp = blockIdx.x * 8 + w; grp < G; grp += nwarps) {
        int base = grp << 4;
        uint32_t xw[2][8], msk[2];
        int tt[2];
        #pragma unroll
        for (int j = 0; j < 2; j++) {
            int node = base + g + 8 * j;
            tt[j] = __ldg(&ntype[node]);
            msk[j] = (tt[j] == 0) ? 0xFFFFFFFFu : 0u;
            #pragma unroll
            for (int m = 0; m < 4; m++) {
                float4 f = xp4[(size_t)node * 16 + 4 * m + tq];
                xw[j][2 * m]     = pack_h2(f.x, f.y);   // x word 8m+2tq
                xw[j][2 * m + 1] = pack_h2(f.z, f.w);   // x word 8m+2tq+1
            }
        }

        float acc[8][4];
        #pragma unroll
        for (int nt = 0; nt < 8; nt++)
            #pragma unroll
            for (int jj = 0; jj < 4; jj++) acc[nt][jj] = 0.f;

        #pragma unroll
        for (int kb = 0; kb < 8; kb++) {
            int p = kb & 3;
            uint32_t s0 = (kb < 4) ? msk[0] : ~msk[0];
            uint32_t s1 = (kb < 4) ? msk[1] : ~msk[1];
            uint32_t a0 = xw[0][2 * p] & s0;
            uint32_t a2 = xw[0][2 * p + 1] & s0;
            uint32_t a1 = xw[1][2 * p] & s1;
            uint32_t a3 = xw[1][2 * p + 1] & s1;
            #pragma unroll
            for (int ntp = 0; ntp < 4; ntp++) {
                uint4 bw = Wf[(kb * 4 + ntp) * 32 + lane];
                mma_f16(acc[2 * ntp], a0, a1, a2, a3, bw.x, bw.y);
                mma_f16(acc[2 * ntp + 1], a0, a1, a2, a3, bw.z, bw.w);
            }
        }

        #pragma unroll
        for (int j = 0; j < 2; j++) {
            int node = base + g + 8 * j;
            int t = tt[j];
            uint2* xdst = (uint2*)(xh32 + (size_t)node * 32);
            #pragma unroll
            for (int m = 0; m < 4; m++)
                xdst[(8 * m + 2 * tq) >> 1] = make_uint2(xw[j][2 * m], xw[j][2 * m + 1]);
            #pragma unroll
            for (int nt = 0; nt < 8; nt++) {
                int col0 = nt * 8 + 2 * tq;
                float v0 = acc[nt][2 * j + 0] + bc[t * 64 + col0];
                float v1 = acc[nt][2 * j + 1] + bc[t * 64 + col0 + 1];
                h2p[(size_t)node * 32 + nt * 4 + tq] = __floats2half2_rn(v0, v1);
            }
        }
    }
}

// h1 GEMM: A = [x*(t==0)(64) | x*(t==1)(64) | tail(64)], k=192, fp16 inputs
// via 4x LDG.128 per node; fragment slot p: word(p,h) = 16*(p>>1)+4*tq+2*(p&1)+h.
// Tail words 0..23 = aggE; word 24 = (c0,c1), 25 = (c2,0) patched from cursor
// (lane tq==2, slot p=2).  out[node] = acc + b1[t] (FULL write).
__global__ __launch_bounds__(256, 2)
void h1_gemm_kernel(const int* __restrict__ ntype,
                    const float* __restrict__ W1, const float* __restrict__ b1,
                    const float* __restrict__ W5, const float* __restrict__ b5,
                    float* __restrict__ out) {
    extern __shared__ uint32_t smu[];
    uint4* Wf = (uint4*)smu;                 // [12][4][32] uint4 = 24 KB
    float* bc = (float*)(smu + 6144);        // [128]

    const int tid = threadIdx.x;
    const int w = tid >> 5, lane = tid & 31;
    const int g = lane >> 2, tq = lane & 3;

    for (int idx = tid; idx < 1536; idx += 256) {
        int ln = idx & 31;
        int ntp = (idx >> 5) & 3;
        int kb = idx >> 7;                    // 0..11
        int tqf = ln & 3, gf = ln >> 2;
        int col0 = (2 * ntp) * 8 + gf;
        int col1 = col0 + 8;
        auto val = [&](int h, int elem, int outc) -> float {
            if (kb < 8) {
                int ty = kb >> 2, p = kb & 3;
                int wd = 16 * (p >> 1) + 4 * tqf + 2 * (p & 1) + h;
                int hh = 2 * wd + elem;                      // x column
                return W1[(size_t)ty * 4096 + hh * 64 + outc];
            } else {
                int p = kb - 8;
                int wd = 16 * (p >> 1) + 4 * tqf + 2 * (p & 1) + h;
                if (wd < 24) {
                    int t = wd >> 3, colf = 2 * (wd & 7) + elem;
                    return W5[(size_t)(t * 16 + colf) * 64 + outc];
                }
                if (wd == 24) return b5[elem * 64 + outc];           // c0,c1
                if (wd == 25) return (elem == 0) ? b5[128 + outc] : 0.f;  // c2
                return 0.f;
            }
        };
        uint4 wv;
        wv.x = pack_h2(val(0, 0, col0), val(0, 1, col0));
        wv.y = pack_h2(val(1, 0, col0), val(1, 1, col0));
        wv.z = pack_h2(val(0, 0, col1), val(0, 1, col1));
        wv.w = pack_h2(val(1, 0, col1), val(1, 1, col1));
        Wf[idx] = wv;
    }
    if (tid < 128) bc[tid] = b1[tid];
    __syncthreads();

    const int G = Nn >> 4;
    const int nwarps = gridDim.x << 3;
    float2* outp = (float2*)out;
    const uint4* xh4 = (const uint4*)g_xh;
    const uint4* ag4 = (const uint4*)g_aggEh;

    for (int grp = blockIdx.x * 8 + w; grp < G; grp += nwarps) {
        int base = grp << 4;
        uint4 xu[2][2], tu[2][2];
        uint32_t msk[2];
        int tt[2];
        #pragma unroll
        for (int j = 0; j < 2; j++) {
            int node = base + g + 8 * j;
            tt[j] = __ldg(&ntype[node]);
            msk[j] = (tt[j] == 0) ? 0xFFFFFFFFu : 0u;
            xu[j][0] = __ldg(&xh4[(size_t)node * 8 + tq]);
            xu[j][1] = __ldg(&xh4[(size_t)node * 8 + tq + 4]);
            tu[j][0] = __ldg(&ag4[(size_t)node * 8 + tq]);
            tu[j][1] = __ldg(&ag4[(size_t)node * 8 + tq + 4]);
            // counts patch: words 24 (=c0,c1) and 25 (=c2,0) live at
            // lane tq==2, slot p=2 (tu[1].x / tu[1].y).
            int cv = __ldg(&g_cur[node]);
            if (tq == 2) {
                int tot = cv & 1023, c1i = (cv >> 10) & 1023, c2i = cv >> 20;
                tu[j][1].x = pack_h2((float)(tot - c1i - c2i), (float)c1i);
                tu[j][1].y = pack_h2((float)c2i, 0.f);
            }
        }

        float acc[8][4];
        #pragma unroll
        for (int nt = 0; nt < 8; nt++)
            #pragma unroll
            for (int jj = 0; jj < 4; jj++) acc[nt][jj] = 0.f;

        auto slot = [&](uint4 uq[2], int p, int h) -> uint32_t {
            uint4 uu = uq[p >> 1];
            return (p & 1) ? (h ? uu.w : uu.z) : (h ? uu.y : uu.x);
        };

        #pragma unroll
        for (int kb = 0; kb < 12; kb++) {
            uint32_t a0, a1, a2, a3;
            if (kb < 8) {
                int p = kb & 3;
                uint32_t s0 = (kb < 4) ? msk[0] : ~msk[0];
                uint32_t s1 = (kb < 4) ? msk[1] : ~msk[1];
                a0 = slot(xu[0], p, 0) & s0;
                a2 = slot(xu[0], p, 1) & s0;
                a1 = slot(xu[1], p, 0) & s1;
                a3 = slot(xu[1], p, 1) & s1;
            } else {
                int p = kb - 8;
                a0 = slot(tu[0], p, 0); a2 = slot(tu[0], p, 1);
                a1 = slot(tu[1], p, 0); a3 = slot(tu[1], p, 1);
            }
            #pragma unroll
            for (int ntp = 0; ntp < 4; ntp++) {
                uint4 bw = Wf[(kb * 4 + ntp) * 32 + lane];
                mma_f16(acc[2 * ntp], a0, a1, a2, a3, bw.x, bw.y);
                mma_f16(acc[2 * ntp + 1], a0, a1, a2, a3, bw.z, bw.w);
            }
        }

        #pragma unroll
        for (int j = 0; j < 2; j++) {
            int node = base + g + 8 * j;
            int t = tt[j];
            #pragma unroll
            for (int nt = 0; nt < 8; nt++) {
                int col0 = nt * 8 + 2 * tq;
                float v0 = acc[nt][2 * j + 0] + bc[t * 64 + col0];
                float v1 = acc[nt][2 * j + 1] + bc[t * 64 + col0 + 1];
                outp[(size_t)node * 32 + nt * 4 + tq] = make_float2(v0, v1);
            }
        }
    }
}

// Bucket gather: out[dst] += sum h2h[src]; 8 lanes/node, uint4 loads.
__global__ __launch_bounds__(256)
void gatherH_kernel(float* __restrict__ out) {
    int tid = threadIdx.x;
    int node = blockIdx.x * 32 + (tid >> 3);
    int q = tid & 7;
    if (node >= Nn) return;
    int deg = g_cur[node] & 1023;
    if (deg > CAP) deg = CAP;
    if (deg == 0) return;

    const uint4* H = (const uint4*)g_h2h;
    const int* sl = &g_slots[(size_t)node * CAP];
    float acc[8];
    #pragma unroll
    for (int u = 0; u < 8; u++) acc[u] = 0.f;

    auto add8 = [&](uint4 hv) {
        float2 f0 = __half22float2(*(__half2*)&hv.x);
        float2 f1 = __half22float2(*(__half2*)&hv.y);
        float2 f2 = __half22float2(*(__half2*)&hv.z);
        float2 f3 = __half22float2(*(__half2*)&hv.w);
        acc[0] += f0.x; acc[1] += f0.y; acc[2] += f1.x; acc[3] += f1.y;
        acc[4] += f2.x; acc[5] += f2.y; acc[6] += f3.x; acc[7] += f3.y;
    };

    int i = 0;
    for (; i + 8 <= deg; i += 8) {
        int s[8];
        #pragma unroll
        for (int u = 0; u < 8; u++) s[u] = __ldg(&sl[i + u]);
        uint4 v[8];
        #pragma unroll
        for (int u = 0; u < 8; u++) v[u] = __ldg(&H[(size_t)s[u] * 8 + q]);
        #pragma unroll
        for (int u = 0; u < 8; u++) add8(v[u]);
    }
    for (; i + 4 <= deg; i += 4) {
        int s[4];
        #pragma unroll
        for (int u = 0; u < 4; u++) s[u] = __ldg(&sl[i + u]);
        uint4 v[4];
        #pragma unroll
        for (int u = 0; u < 4; u++) v[u] = __ldg(&H[(size_t)s[u] * 8 + q]);
        #pragma unroll
        for (int u = 0; u < 4; u++) add8(v[u]);
    }
    for (; i < deg; i++) add8(__ldg(&H[(size_t)__ldg(&sl[i]) * 8 + q]));

    float4* o4 = (float4*)out;
    float4 oa = o4[(size_t)node * 16 + 2 * q];
    float4 ob = o4[(size_t)node * 16 + 2 * q + 1];
    oa.x += acc[0]; oa.y += acc[1]; oa.z += acc[2]; oa.w += acc[3];
    ob.x += acc[4]; ob.y += acc[5]; ob.z += acc[6]; ob.w += acc[7];
    o4[(size_t)node * 16 + 2 * q] = oa;
    o4[(size_t)node * 16 + 2 * q + 1] = ob;
}

// Overflow edges (deg > CAP): add the missed W2[t]*x[src] + b2[t] to out[dst].
// (aggE/counts already include overflow edges via the unconditional scatter.)
__global__ void ovf_kernel(const float* __restrict__ x,
                           const int* __restrict__ ntype,
                           const float* __restrict__ W2,
                           const float* __restrict__ b2,
                           float* __restrict__ out) {
    int n = g_ovf_cnt;
    if (n > 8192) n = 8192;
    int wid = (blockIdx.x * blockDim.x + threadIdx.x) >> 5;
    int lane = threadIdx.x & 31;
    int nwarps = (gridDim.x * blockDim.x) >> 5;
    for (int ei = wid; ei < n; ei += nwarps) {
        int2 sd = g_ovf[ei];
        int src = sd.x, dst = sd.y;
        int t = ntype[src];
        int c = lane * 2;
        float s0 = b2[t * 64 + c], s1 = b2[t * 64 + c + 1];
        for (int k = 0; k < 64; k++) {
            float xv = __ldg(&x[(size_t)src * 64 + k]);
            s0 += xv * __ldg(&W2[(size_t)t * 4096 + k * 64 + c]);
            s1 += xv * __ldg(&W2[(size_t)t * 4096 + k * 64 + c + 1]);
        }
        atomicAdd(&out[(size_t)dst * 64 + c], s0);
        atomicAdd(&out[(size_t)dst * 64 + c + 1], s1);
    }
}

// ---------------- launch ----------------
extern "C" void kernel_launch(void* const* d_in, const int* in_sizes, int n_in,
                              void* d_out, int out_size) {
    const float *x = nullptr, *ef = nullptr;
    const float *W[4] = {nullptr, nullptr, nullptr, nullptr};
    const float *B[4] = {nullptr, nullptr, nullptr, nullptr};
    const float *W5 = nullptr, *b5 = nullptr;
    const int *ntype = nullptr, *esrc = nullptr, *edst = nullptr, *etype = nullptr;
    int wI = 0, bI = 0, mI = 0;
    for (int i = 0; i < n_in; i++) {
        long s = in_sizes[i];
        const void* p = d_in[i];
        if (s == (long)Nn * 64)       x = (const float*)p;
        else if (s == (long)Mm * 16)  ef = (const float*)p;
        else if (s == Nn)             ntype = (const int*)p;
        else if (s == Mm) {
            if (mI == 0) esrc = (const int*)p;
            else if (mI == 1) edst = (const int*)p;
            else etype = (const int*)p;
            mI++;
        }
        else if (s == 2 * 64 * 64) { if (wI < 4) W[wI++] = (const float*)p; }
        else if (s == 2 * 64)      { if (bI < 4) B[bI++] = (const float*)p; }
        else if (s == 3 * 16 * 64) W5 = (const float*)p;
        else if (s == 3 * 64)      b5 = (const float*)p;
    }
    float* out = (float*)d_out;

    cudaStream_t s2;
    cudaEvent_t evFork, evJoin;
    bool forked = (cudaStreamCreateWithFlags(&s2, cudaStreamNonBlocking) == cudaSuccess)
               && (cudaEventCreateWithFlags(&evFork, cudaEventDisableTiming) == cudaSuccess)
               && (cudaEventCreateWithFlags(&evJoin, cudaEventDisableTiming) == cudaSuccess);

    const int h2_smem = 4096 * 4 + 128 * 4;   // 16.5 KB
    const int h1_smem = 6144 * 4 + 128 * 4;   // 24.5 KB

    if (forked) {
        cudaEventRecord(evFork, 0);
        cudaStreamWaitEvent(s2, evFork, 0);
        h2_gemm_kernel<<<296, 256, h2_smem, s2>>>(x, ntype, W[1], B[1]);
        cudaEventRecord(evJoin, s2);
    } else {
        h2_gemm_kernel<<<296, 256, h2_smem>>>(x, ntype, W[1], B[1]);
    }

    zero_kernel<<<1024, 256>>>();
    edge_scatter_kernel<<<(Mm * 2 + 255) / 256, 256>>>(ef, esrc, edst, etype);
    if (forked) cudaStreamWaitEvent(0, evJoin, 0);
    h1_gemm_kernel<<<296, 256, h1_smem>>>(ntype, W[0], B[0], W5, b5, out);
    gatherH_kernel<<<(Nn + 31) / 32, 256>>>(out);
    ovf_kernel<<<8, 256>>>(x, ntype, W[1], B[1], out);
}